// round 7
// baseline (speedup 1.0000x reference)
#include <cuda_runtime.h>
#include <math.h>

#define NCLS 40
#define QN 100
#define BN 4
#define HW 65536
#define THREADS 256
#define PPT 4
#define PIX (THREADS*PPT)          // 1024 pixels per block
#define NC1 (NCLS+1)
#define QG 5                       // q-groups
#define QPG (QN/QG)                // 20 queries per group (even -> 2q per barrier)
#define NPIX (BN*HW)               // 262144 pixels
#define PIXBLK (HW/PIX)            // 64 pixel-blocks per image
#define NBLK_MAIN (QG*BN*PIXBLK)   // 1280
#define FIN_BLOCKS 4

// ---- scratch (device globals; no allocation allowed) ----
__device__ float g_inter[BN*QN*NCLS];
__device__ float g_src[BN*QN];
__device__ int   g_counts[BN*QN*NCLS];
__device__ int   g_tsum[BN*NCLS];
__device__ float g_ce_sum;
__device__ int   g_nvalid;
__device__ float g_ce2, g_dice2;
__device__ int   g_done;
// per-pixel per-group partials (~17 MB)
__device__ float4 g_pssum[QG][NPIX/4];
__device__ float4 g_pmax [QG][NPIX/4];
__device__ float4 g_pxt  [QG][NPIX/4];
__device__ uchar4 g_pamax[QG][NPIX/4];

__global__ void zero_k() {
    int i = blockIdx.x * blockDim.x + threadIdx.x;
    if (i < BN*QN*NCLS) { g_inter[i] = 0.f; g_counts[i] = 0; }
    if (i < BN*QN) g_src[i] = 0.f;
    if (i < BN*NCLS) g_tsum[i] = 0;
    if (i == 0) { g_ce_sum = 0.f; g_nvalid = 0; g_ce2 = 0.f; g_dice2 = 0.f; g_done = 0; }
}

// Streaming pass: block = (q-group g, image, 1024 contiguous pixels).
// 2 q's per barrier using 4 staging buffers; float4/thread; register prefetch.
// inter[q][c] accumulated via class-sorted shared staging.
__global__ __launch_bounds__(THREADS) void main_k(
    const float* __restrict__ masks, const int* __restrict__ targets)
{
    __shared__ __align__(16) float sig_sh[4][PIX];  // 16 KB, 4-way: 1 barrier / 2 q
    __shared__ float inter_sh[QPG*NC1];             // 3.3 KB, class 40 = ignore bin
    __shared__ unsigned char cls_sorted[PIX];
    __shared__ int s_cnt[NC1];
    __shared__ int s_base[NC1];
    __shared__ int s_cur[NC1];

    const int tid = threadIdx.x;
    const int g   = blockIdx.x / (BN*PIXBLK);
    const int rem = blockIdx.x % (BN*PIXBLK);
    const int img = rem / PIXBLK;
    const int blk = rem % PIXBLK;
    const int q0  = g*QPG;
    const int pixbase = img*HW + blk*PIX;

    const float4* base4 = reinterpret_cast<const float4*>(
        masks + (size_t)img*QN*HW + (size_t)blk*PIX);
    const int stride4 = HW/4;
    // issue first two q loads early to overlap the sort phase
    float4 cur0 = base4[(size_t)q0*stride4 + tid];
    float4 cur1 = base4[(size_t)(q0+1)*stride4 + tid];

    for (int i = tid; i < QPG*NC1; i += THREADS) inter_sh[i] = 0.f;
    for (int i = tid; i < NC1; i += THREADS) s_cnt[i] = 0;
    __syncthreads();

    // ---- classes (4 contiguous pixels/thread) + counting sort by class ----
    int myc[PPT], mypos[PPT];
    {
        int4 t4 = reinterpret_cast<const int4*>(targets + pixbase)[tid];
        int tt[PPT] = {t4.x, t4.y, t4.z, t4.w};
        #pragma unroll
        for (int j = 0; j < PPT; j++) {
            myc[j] = ((unsigned)tt[j] < (unsigned)NCLS) ? tt[j] : NCLS; // 40 == ignore
            atomicAdd(&s_cnt[myc[j]], 1);
        }
    }
    __syncthreads();
    if (tid == 0) {
        int r = 0;
        for (int c = 0; c < NC1; c++) { s_base[c] = r; r += s_cnt[c]; }
    }
    __syncthreads();
    for (int i = tid; i < NC1; i += THREADS) s_cur[i] = s_base[i];
    __syncthreads();
    #pragma unroll
    for (int j = 0; j < PPT; j++) {
        mypos[j] = atomicAdd(&s_cur[myc[j]], 1);
        cls_sorted[mypos[j]] = (unsigned char)myc[j];
    }
    __syncthreads();
    int accCls[PPT];
    #pragma unroll
    for (int j = 0; j < PPT; j++) accCls[j] = (int)cls_sorted[tid*PPT + j];

    float ssum[PPT], mmax[PPT], xt[PPT];
    int amax[PPT];
    #pragma unroll
    for (int j = 0; j < PPT; j++) { ssum[j] = 0.f; mmax[j] = -1e30f; xt[j] = 0.f; amax[j] = q0; }

    for (int qi = 0; qi < QPG; qi += 2) {
        // prefetch next pair before any dependent work / barrier
        float4 nxt0, nxt1;
        if (qi + 2 < QPG) {
            nxt0 = base4[(size_t)(q0+qi+2)*stride4 + tid];
            nxt1 = base4[(size_t)(q0+qi+3)*stride4 + tid];
        } else {
            nxt0 = make_float4(0.f,0.f,0.f,0.f);
            nxt1 = make_float4(0.f,0.f,0.f,0.f);
        }
        const int bsel = qi & 2;                 // 0,2,0,2,... buffer pair
        float* sb0 = sig_sh[bsel];
        float* sb1 = sig_sh[bsel+1];
        {
            const int q = q0 + qi;
            float xv[PPT] = {cur0.x, cur0.y, cur0.z, cur0.w};
            #pragma unroll
            for (int j = 0; j < PPT; j++) {
                float x = xv[j];
                if (x > mmax[j]) { mmax[j] = x; amax[j] = q; }
                xt[j] = (q == myc[j]) ? x : xt[j];
                float xc = fminf(fmaxf(x, -15.f), 15.f);
                float t = __expf(xc);
                ssum[j] += t;
                sb0[mypos[j]] = __fdividef(t, 1.f + t);
            }
        }
        {
            const int q = q0 + qi + 1;
            float xv[PPT] = {cur1.x, cur1.y, cur1.z, cur1.w};
            #pragma unroll
            for (int j = 0; j < PPT; j++) {
                float x = xv[j];
                if (x > mmax[j]) { mmax[j] = x; amax[j] = q; }
                xt[j] = (q == myc[j]) ? x : xt[j];
                float xc = fminf(fmaxf(x, -15.f), 15.f);
                float t = __expf(xc);
                ssum[j] += t;
                sb1[mypos[j]] = __fdividef(t, 1.f + t);
            }
        }
        __syncthreads();
        // gather both q's: 4 consecutive class-sorted slots -> mostly one run
        #pragma unroll
        for (int s = 0; s < 2; s++) {
            const float* sbuf = s ? sb1 : sb0;
            float4 v = reinterpret_cast<const float4*>(sbuf)[tid];
            float* ip = &inter_sh[(qi+s)*NC1];
            float a = v.x; int c = accCls[0];
            if (accCls[1] == c) a += v.y; else { atomicAdd(ip + c, a); c = accCls[1]; a = v.y; }
            if (accCls[2] == c) a += v.z; else { atomicAdd(ip + c, a); c = accCls[2]; a = v.z; }
            if (accCls[3] == c) a += v.w; else { atomicAdd(ip + c, a); c = accCls[3]; a = v.w; }
            atomicAdd(ip + c, a);
        }
        cur0 = nxt0; cur1 = nxt1;
        // no trailing barrier: buffer pair alternates; next iteration's barrier
        // separates these gathers from the next reuse of this pair
    }

    // ---- write per-pixel partials for combine_k ----
    {
        const int p4 = pixbase/4 + tid;
        g_pssum[g][p4] = make_float4(ssum[0], ssum[1], ssum[2], ssum[3]);
        g_pmax [g][p4] = make_float4(mmax[0], mmax[1], mmax[2], mmax[3]);
        g_pxt  [g][p4] = make_float4(xt[0], xt[1], xt[2], xt[3]);
        g_pamax[g][p4] = make_uchar4((unsigned char)amax[0], (unsigned char)amax[1],
                                     (unsigned char)amax[2], (unsigned char)amax[3]);
    }
    __syncthreads();   // orders all inter_sh atomics before flush

    // ---- flush inter_sh -> global (src_sum = sum over all 41 bins incl. ignore) ----
    for (int qi = tid; qi < QPG; qi += THREADS) {
        float ss = 0.f;
        const int q = q0 + qi;
        #pragma unroll 1
        for (int c = 0; c < NC1; c++) {
            float v = inter_sh[qi*NC1 + c];
            ss += v;
            if (c < NCLS) atomicAdd(&g_inter[(img*QN + q)*NCLS + c], v);
        }
        atomicAdd(&g_src[img*QN + q], ss);
    }
}

// Cross-group combine: per-pixel ce_mask numerator, n_valid, assignment counts,
// and the per-image class histogram (== tsum, since Sum_q counts is q-free).
__global__ __launch_bounds__(THREADS) void combine_k(const int* __restrict__ targets)
{
    __shared__ float s_red[THREADS];
    __shared__ int hist[NCLS];
    const int tid = threadIdx.x;
    const int j = blockIdx.x * THREADS + tid;      // float4 pixel group
    const int img = (int)(((size_t)blockIdx.x * THREADS * 4) >> 16); // block within one image

    for (int i = tid; i < NCLS; i += THREADS) hist[i] = 0;
    __syncthreads();

    float4 ssum = g_pssum[0][j];
    float4 mmax = g_pmax [0][j];
    float4 xt   = g_pxt  [0][j];
    uchar4 am   = g_pamax[0][j];
    #pragma unroll
    for (int g = 1; g < QG; g++) {
        float4 s2 = g_pssum[g][j];
        float4 m2 = g_pmax [g][j];
        float4 x2 = g_pxt  [g][j];
        uchar4 a2 = g_pamax[g][j];
        ssum.x += s2.x; ssum.y += s2.y; ssum.z += s2.z; ssum.w += s2.w;
        xt.x += x2.x; xt.y += x2.y; xt.z += x2.z; xt.w += x2.w;
        if (m2.x > mmax.x) { mmax.x = m2.x; am.x = a2.x; }
        if (m2.y > mmax.y) { mmax.y = m2.y; am.y = a2.y; }
        if (m2.z > mmax.z) { mmax.z = m2.z; am.z = a2.z; }
        if (m2.w > mmax.w) { mmax.w = m2.w; am.w = a2.w; }
    }
    int4 t4 = reinterpret_cast<const int4*>(targets)[j];

    float ce_l = 0.f, nv = 0.f;
    int tt[PPT] = {t4.x, t4.y, t4.z, t4.w};
    float ssv[PPT] = {ssum.x, ssum.y, ssum.z, ssum.w};
    float xtv[PPT] = {xt.x, xt.y, xt.z, xt.w};
    int amv[PPT] = {am.x, am.y, am.z, am.w};
    #pragma unroll
    for (int k = 0; k < PPT; k++) {
        if ((unsigned)tt[k] < (unsigned)NCLS) {
            ce_l += __logf(ssv[k]) - xtv[k];       // lse - x[target]
            nv += 1.f;
            atomicAdd(&hist[tt[k]], 1);
            atomicAdd(&g_counts[(img*QN + amv[k])*NCLS + tt[k]], 1);
        }
    }
    s_red[tid] = ce_l; __syncthreads();
    for (int s = THREADS/2; s > 0; s >>= 1) { if (tid < s) s_red[tid] += s_red[tid+s]; __syncthreads(); }
    if (tid == 0) atomicAdd(&g_ce_sum, s_red[0]);
    __syncthreads();
    s_red[tid] = nv; __syncthreads();
    for (int s = THREADS/2; s > 0; s >>= 1) { if (tid < s) s_red[tid] += s_red[tid+s]; __syncthreads(); }
    if (tid == 0) atomicAdd(&g_nvalid, (int)s_red[0]);
    // flush class histogram
    for (int c = tid; c < NCLS; c += THREADS)
        if (hist[c]) atomicAdd(&g_tsum[img*NCLS + c], hist[c]);
}

// Parallel final reduction: 4 blocks over 400 (b,q) items; last block finalizes.
__global__ __launch_bounds__(128) void fin_k(const float* __restrict__ logits,
                                             float* __restrict__ out)
{
    __shared__ float tsum_sh[BN*NCLS];
    __shared__ float pres_sh[NCLS];
    __shared__ float red[128];
    const int tid = threadIdx.x;

    for (int i = tid; i < BN*NCLS; i += 128) tsum_sh[i] = (float)g_tsum[i];
    __syncthreads();
    for (int c = tid; c < NCLS; c += 128) {
        float t = 0.f;
        for (int b = 0; b < BN; b++) t += tsum_sh[b*NCLS + c];
        pres_sh[c] = (t > 0.f) ? 1.f : 0.f;
    }
    __syncthreads();

    const int i = blockIdx.x * 128 + tid;          // (b,q) item, < 400
    float ce_acc = 0.f, dice_acc = 0.f;
    if (i < BN*QN) {
        const int b = i / QN;
        // mode label = argmax of counts (ties -> smallest class); empty -> NCLS
        const int* cp = &g_counts[i*NCLS];
        int bestc = NCLS, bestcnt = 0;
        #pragma unroll 4
        for (int c = 0; c < NCLS; c++) { int v = __ldg(cp + c); if (v > bestcnt) { bestcnt = v; bestc = c; } }
        if (bestc < NCLS) {
            const float* lg = logits + i*NC1;
            float m = -1e30f;
            for (int c = 0; c < NC1; c++) m = fmaxf(m, __ldg(lg + c));
            float s = 0.f;
            for (int c = 0; c < NC1; c++) s += __expf(__ldg(lg + c) - m);
            float nll = m + __logf(s) - __ldg(lg + bestc); // weight = 1 for c < NCLS
            float p = __expf(-nll);
            float om = 1.f - p;
            ce_acc = om * om * nll;
        }
        float ss = g_src[i];
        #pragma unroll 4
        for (int c = 0; c < NCLS; c++) {
            dice_acc += pres_sh[c] * 2.f * __ldg(&g_inter[i*NCLS + c])
                        / (ss + tsum_sh[b*NCLS + c] + 1e-8f);
        }
    }

    red[tid] = ce_acc; __syncthreads();
    for (int s = 64; s > 0; s >>= 1) { if (tid < s) red[tid] += red[tid+s]; __syncthreads(); }
    float ce_blk = red[0]; __syncthreads();
    red[tid] = dice_acc; __syncthreads();
    for (int s = 64; s > 0; s >>= 1) { if (tid < s) red[tid] += red[tid+s]; __syncthreads(); }
    float dice_blk = red[0];

    __shared__ int s_last;
    if (tid == 0) {
        atomicAdd(&g_ce2, ce_blk);
        atomicAdd(&g_dice2, dice_blk);
        __threadfence();
        s_last = (atomicAdd(&g_done, 1) == FIN_BLOCKS - 1);
    }
    __syncthreads();
    if (s_last && tid == 0) {
        float npres = 0.f;
        for (int c = 0; c < NCLS; c++) npres += pres_sh[c];
        float ce_tot   = *(volatile float*)&g_ce2;
        float dice_tot = *(volatile float*)&g_dice2;
        float loss_ce = ce_tot / (float)(BN*QN);
        float ce_mask = g_ce_sum / fmaxf((float)g_nvalid, 1.f);
        float dice_loss = (npres - dice_tot / (float)(BN*QN)) / (float)NCLS;
        out[0] = 2.f*loss_ce + 5.f*ce_mask + 5.f*dice_loss;
    }
}

extern "C" void kernel_launch(void* const* d_in, const int* in_sizes, int n_in,
                              void* d_out, int out_size)
{
    const float* logits  = (const float*)d_in[0];   // [4,100,41] f32
    const float* masks   = (const float*)d_in[1];   // [4,100,256,256] f32
    const int*   targets = (const int*)d_in[2];     // [4,256,256] i32
    float* out = (float*)d_out;

    zero_k<<<(BN*QN*NCLS + 255)/256, 256>>>();
    main_k<<<NBLK_MAIN, THREADS>>>(masks, targets);
    combine_k<<<NPIX/4/THREADS, THREADS>>>(targets);
    fin_k<<<FIN_BLOCKS, 128>>>(logits, out);
}

// round 10
// speedup vs baseline: 1.7299x; 1.7299x over previous
#include <cuda_runtime.h>
#include <math.h>

#define NCLS 40
#define QN 100
#define BN 4
#define HW 65536
#define THREADS 256
#define PPT 4
#define PIX (THREADS*PPT)          // 1024 pixels per block
#define NC1 (NCLS+1)
#define QG 4                       // q-groups
#define QPG (QN/QG)                // 25 queries per group
#define NPIX (BN*HW)               // 262144 pixels
#define PIXBLK (HW/PIX)            // 64 pixel-blocks per image
#define NBLK_MAIN (QG*BN*PIXBLK)   // 1024
#define FIN_WARPS (BN*QN)          // 400
#define FIN_BLOCKS 100             // 4 warps per block

// ---- scratch (device globals; no allocation allowed) ----
__device__ float g_inter[BN*QN*NCLS];
__device__ float g_src[BN*QN];
__device__ int   g_counts[BN*QN*NCLS];
__device__ int   g_tsum[BN*NCLS];
__device__ float g_ce_sum;
__device__ int   g_nvalid;
__device__ float g_ce2, g_dice2;
__device__ int   g_done;
// per-pixel per-group partials (~13.6 MB)
__device__ float4 g_pssum[QG][NPIX/4];
__device__ float4 g_pmax [QG][NPIX/4];
__device__ float4 g_pxt  [QG][NPIX/4];
__device__ uchar4 g_pamax[QG][NPIX/4];

__global__ void zero_k() {
    int i = blockIdx.x * blockDim.x + threadIdx.x;
    if (i < BN*QN*NCLS) { g_inter[i] = 0.f; g_counts[i] = 0; }
    if (i < BN*QN) g_src[i] = 0.f;
    if (i < BN*NCLS) g_tsum[i] = 0;
    if (i == 0) { g_ce_sum = 0.f; g_nvalid = 0; g_ce2 = 0.f; g_dice2 = 0.f; g_done = 0; }
}

// Streaming pass (round-6 proven config): block = (q-group, image, 1024 pixels).
// One q per barrier, float4/thread, depth-1 register prefetch.
__global__ __launch_bounds__(THREADS) void main_k(
    const float* __restrict__ masks, const int* __restrict__ targets)
{
    __shared__ __align__(16) float sig_sh[2][PIX];  // double buffer: 1 barrier per q
    __shared__ float inter_sh[QPG*NC1];             // 4.1 KB, class 40 = ignore bin
    __shared__ unsigned char cls_sorted[PIX];
    __shared__ int s_cnt[NC1];
    __shared__ int s_base[NC1];
    __shared__ int s_cur[NC1];

    const int tid = threadIdx.x;
    const int g   = blockIdx.x / (BN*PIXBLK);
    const int rem = blockIdx.x % (BN*PIXBLK);
    const int img = rem / PIXBLK;
    const int blk = rem % PIXBLK;
    const int q0  = g*QPG;
    const int pixbase = img*HW + blk*PIX;

    for (int i = tid; i < QPG*NC1; i += THREADS) inter_sh[i] = 0.f;
    for (int i = tid; i < NC1; i += THREADS) s_cnt[i] = 0;
    __syncthreads();

    // ---- classes (4 contiguous pixels/thread) + counting sort by class ----
    int myc[PPT], mypos[PPT];
    {
        int4 t4 = reinterpret_cast<const int4*>(targets + pixbase)[tid];
        int tt[PPT] = {t4.x, t4.y, t4.z, t4.w};
        #pragma unroll
        for (int j = 0; j < PPT; j++) {
            myc[j] = ((unsigned)tt[j] < (unsigned)NCLS) ? tt[j] : NCLS; // 40 == ignore
            atomicAdd(&s_cnt[myc[j]], 1);
        }
    }
    __syncthreads();
    if (tid == 0) {
        int r = 0;
        for (int c = 0; c < NC1; c++) { s_base[c] = r; r += s_cnt[c]; }
    }
    __syncthreads();
    for (int i = tid; i < NC1; i += THREADS) s_cur[i] = s_base[i];
    __syncthreads();
    #pragma unroll
    for (int j = 0; j < PPT; j++) {
        mypos[j] = atomicAdd(&s_cur[myc[j]], 1);
        cls_sorted[mypos[j]] = (unsigned char)myc[j];
    }
    __syncthreads();
    int accCls[PPT];
    #pragma unroll
    for (int j = 0; j < PPT; j++) accCls[j] = (int)cls_sorted[tid*PPT + j];

    float ssum[PPT], mmax[PPT], xt[PPT];
    int amax[PPT];
    #pragma unroll
    for (int j = 0; j < PPT; j++) { ssum[j] = 0.f; mmax[j] = -1e30f; xt[j] = 0.f; amax[j] = q0; }

    const float4* base4 = reinterpret_cast<const float4*>(
        masks + (size_t)img*QN*HW + (size_t)blk*PIX);
    const int stride4 = HW/4;

    float4 cur = base4[(size_t)q0*stride4 + tid];      // prefetch first q
    for (int qi = 0; qi < QPG; qi++) {
        const int q = q0 + qi;
        // prefetch next q before any dependent work / barrier
        float4 nxt;
        if (qi + 1 < QPG) nxt = base4[(size_t)(q+1)*stride4 + tid];
        else nxt = make_float4(0.f, 0.f, 0.f, 0.f);

        float xv[PPT] = {cur.x, cur.y, cur.z, cur.w};
        float* sbuf = sig_sh[qi & 1];
        #pragma unroll
        for (int j = 0; j < PPT; j++) {
            float x = xv[j];
            if (x > mmax[j]) { mmax[j] = x; amax[j] = q; }
            xt[j] = (q == myc[j]) ? x : xt[j];
            float xc = fminf(fmaxf(x, -15.f), 15.f);
            float t = __expf(xc);              // one exp serves both lse and sigmoid
            ssum[j] += t;
            float sg = __fdividef(t, 1.f + t); // sigmoid
            sbuf[mypos[j]] = sg;               // scatter to class-sorted slot
        }
        __syncthreads();
        // accumulate: 4 consecutive class-sorted slots -> mostly one run
        float4 v = reinterpret_cast<const float4*>(sbuf)[tid];
        float* ip = &inter_sh[qi*NC1];
        float a = v.x; int c = accCls[0];
        if (accCls[1] == c) a += v.y; else { atomicAdd(ip + c, a); c = accCls[1]; a = v.y; }
        if (accCls[2] == c) a += v.z; else { atomicAdd(ip + c, a); c = accCls[2]; a = v.z; }
        if (accCls[3] == c) a += v.w; else { atomicAdd(ip + c, a); c = accCls[3]; a = v.w; }
        atomicAdd(ip + c, a);
        cur = nxt;
        // no 2nd barrier: next q writes the other buffer; its barrier orders reuse
    }

    // ---- write per-pixel partials for combine_k ----
    {
        const int p4 = pixbase/4 + tid;
        g_pssum[g][p4] = make_float4(ssum[0], ssum[1], ssum[2], ssum[3]);
        g_pmax [g][p4] = make_float4(mmax[0], mmax[1], mmax[2], mmax[3]);
        g_pxt  [g][p4] = make_float4(xt[0], xt[1], xt[2], xt[3]);
        g_pamax[g][p4] = make_uchar4((unsigned char)amax[0], (unsigned char)amax[1],
                                     (unsigned char)amax[2], (unsigned char)amax[3]);
    }
    __syncthreads();   // orders all inter_sh atomics before flush

    // ---- flush inter_sh -> global (src_sum = sum over all 41 bins incl. ignore) ----
    for (int qi = tid; qi < QPG; qi += THREADS) {
        float ss = 0.f;
        const int q = q0 + qi;
        #pragma unroll 1
        for (int c = 0; c < NC1; c++) {
            float v = inter_sh[qi*NC1 + c];
            ss += v;
            if (c < NCLS) atomicAdd(&g_inter[(img*QN + q)*NCLS + c], v);
        }
        atomicAdd(&g_src[img*QN + q], ss);
    }
}

// Cross-group combine: per-pixel ce_mask numerator, n_valid, assignment counts,
// and the per-image class histogram (== tsum, since Sum_q counts is q-free).
__global__ __launch_bounds__(THREADS) void combine_k(const int* __restrict__ targets)
{
    __shared__ float s_red[THREADS];
    __shared__ int hist[NCLS];
    const int tid = threadIdx.x;
    const int j = blockIdx.x * THREADS + tid;      // float4 pixel group
    const int img = (int)(((size_t)blockIdx.x * THREADS * 4) >> 16); // block within one image

    for (int i = tid; i < NCLS; i += THREADS) hist[i] = 0;
    __syncthreads();

    float4 ssum = g_pssum[0][j];
    float4 mmax = g_pmax [0][j];
    float4 xt   = g_pxt  [0][j];
    uchar4 am   = g_pamax[0][j];
    #pragma unroll
    for (int g = 1; g < QG; g++) {
        float4 s2 = g_pssum[g][j];
        float4 m2 = g_pmax [g][j];
        float4 x2 = g_pxt  [g][j];
        uchar4 a2 = g_pamax[g][j];
        ssum.x += s2.x; ssum.y += s2.y; ssum.z += s2.z; ssum.w += s2.w;
        xt.x += x2.x; xt.y += x2.y; xt.z += x2.z; xt.w += x2.w;
        if (m2.x > mmax.x) { mmax.x = m2.x; am.x = a2.x; }
        if (m2.y > mmax.y) { mmax.y = m2.y; am.y = a2.y; }
        if (m2.z > mmax.z) { mmax.z = m2.z; am.z = a2.z; }
        if (m2.w > mmax.w) { mmax.w = m2.w; am.w = a2.w; }
    }
    int4 t4 = reinterpret_cast<const int4*>(targets)[j];

    float ce_l = 0.f, nv = 0.f;
    int tt[PPT] = {t4.x, t4.y, t4.z, t4.w};
    float ssv[PPT] = {ssum.x, ssum.y, ssum.z, ssum.w};
    float xtv[PPT] = {xt.x, xt.y, xt.z, xt.w};
    int amv[PPT] = {am.x, am.y, am.z, am.w};
    #pragma unroll
    for (int k = 0; k < PPT; k++) {
        if ((unsigned)tt[k] < (unsigned)NCLS) {
            ce_l += __logf(ssv[k]) - xtv[k];       // lse - x[target]
            nv += 1.f;
            atomicAdd(&hist[tt[k]], 1);
            atomicAdd(&g_counts[(img*QN + amv[k])*NCLS + tt[k]], 1);
        }
    }
    s_red[tid] = ce_l; __syncthreads();
    for (int s = THREADS/2; s > 0; s >>= 1) { if (tid < s) s_red[tid] += s_red[tid+s]; __syncthreads(); }
    if (tid == 0) atomicAdd(&g_ce_sum, s_red[0]);
    __syncthreads();
    s_red[tid] = nv; __syncthreads();
    for (int s = THREADS/2; s > 0; s >>= 1) { if (tid < s) s_red[tid] += s_red[tid+s]; __syncthreads(); }
    if (tid == 0) atomicAdd(&g_nvalid, (int)s_red[0]);
    // flush class histogram
    for (int c = tid; c < NCLS; c += THREADS)
        if (hist[c]) atomicAdd(&g_tsum[img*NCLS + c], hist[c]);
}

// Warp-per-(b,q) final reduction: lane-parallel mode/CE/dice; last warp finalizes.
__global__ __launch_bounds__(128) void fin_k(const float* __restrict__ logits,
                                             float* __restrict__ out)
{
    const int tid  = threadIdx.x;
    const int lane = tid & 31;
    const int item = blockIdx.x * 4 + (tid >> 5);   // (b,q), < 400
    const int b = item / QN;

    // ---- mode label: packed-key warp max; key = (count<<16)|(NCLS-c) ----
    // larger count wins; tie -> larger (NCLS-c) -> smaller class (matches argmax)
    const int* cp = &g_counts[item*NCLS];
    int c1 = lane, c2 = lane + 32;
    int v1 = __ldg(cp + c1);
    int v2 = (c2 < NCLS) ? __ldg(cp + c2) : 0;
    long long k1 = ((long long)v1 << 16) | (NCLS - c1);
    long long k2 = (c2 < NCLS) ? (((long long)v2 << 16) | (NCLS - c2)) : 0;
    long long key = k1 > k2 ? k1 : k2;
    #pragma unroll
    for (int o = 16; o > 0; o >>= 1) {
        long long other = __shfl_xor_sync(0xffffffff, key, o);
        if (other > key) key = other;
    }
    int bestcnt = (int)(key >> 16);
    int bestc = NCLS - (int)(key & 0xffff);

    // ---- focal CE over 41 logits (warp softmax) ----
    float ce_term = 0.f;
    if (bestcnt > 0) {
        const float* lg = logits + item*NC1;
        float a = __ldg(lg + lane);
        float bb = (lane < NC1 - 32) ? __ldg(lg + lane + 32) : -1e30f;
        float m = fmaxf(a, bb);
        #pragma unroll
        for (int o = 16; o > 0; o >>= 1) m = fmaxf(m, __shfl_xor_sync(0xffffffff, m, o));
        float s = __expf(a - m) + ((lane < NC1 - 32) ? __expf(bb - m) : 0.f);
        #pragma unroll
        for (int o = 16; o > 0; o >>= 1) s += __shfl_xor_sync(0xffffffff, s, o);
        float lgb = __shfl_sync(0xffffffff, (bestc < 32) ? a : bb, bestc & 31);
        float nll = m + __logf(s) - lgb;
        float p = __expf(-nll);
        float om = 1.f - p;
        ce_term = om * om * nll;          // lane-uniform; lane0 will add it
    }

    // ---- dice terms: lanes cover classes lane, lane+32 ----
    float ss = __ldg(&g_src[item]);
    float dice_l = 0.f;
    {
        float t0 = 0.f, t1 = 0.f, t2 = 0.f, t3 = 0.f;
        t0 = (float)__ldg(&g_tsum[0*NCLS + c1]);
        t1 = (float)__ldg(&g_tsum[1*NCLS + c1]);
        t2 = (float)__ldg(&g_tsum[2*NCLS + c1]);
        t3 = (float)__ldg(&g_tsum[3*NCLS + c1]);
        float pres = (t0 + t1 + t2 + t3 > 0.f) ? 1.f : 0.f;
        float tb = (b == 0) ? t0 : (b == 1) ? t1 : (b == 2) ? t2 : t3;
        dice_l += pres * 2.f * __ldg(&g_inter[item*NCLS + c1]) / (ss + tb + 1e-8f);
        if (c2 < NCLS) {
            float u0 = (float)__ldg(&g_tsum[0*NCLS + c2]);
            float u1 = (float)__ldg(&g_tsum[1*NCLS + c2]);
            float u2 = (float)__ldg(&g_tsum[2*NCLS + c2]);
            float u3 = (float)__ldg(&g_tsum[3*NCLS + c2]);
            float pres2 = (u0 + u1 + u2 + u3 > 0.f) ? 1.f : 0.f;
            float ub = (b == 0) ? u0 : (b == 1) ? u1 : (b == 2) ? u2 : u3;
            dice_l += pres2 * 2.f * __ldg(&g_inter[item*NCLS + c2]) / (ss + ub + 1e-8f);
        }
    }
    #pragma unroll
    for (int o = 16; o > 0; o >>= 1) dice_l += __shfl_xor_sync(0xffffffff, dice_l, o);

    bool last = false;
    if (lane == 0) {
        atomicAdd(&g_ce2, ce_term);
        atomicAdd(&g_dice2, dice_l);
        __threadfence();
        last = (atomicAdd(&g_done, 1) == FIN_WARPS - 1);
    }
    if (__shfl_sync(0xffffffff, last ? 1 : 0, 0)) {
        // finalizing warp: npres via lanes
        float pr = 0.f;
        if (lane < NCLS) {
            int t = __ldg(&g_tsum[0*NCLS + lane]) + __ldg(&g_tsum[1*NCLS + lane])
                  + __ldg(&g_tsum[2*NCLS + lane]) + __ldg(&g_tsum[3*NCLS + lane]);
            pr = (t > 0) ? 1.f : 0.f;
        }
        float pr2 = 0.f;
        if (lane + 32 < NCLS) {
            int t = __ldg(&g_tsum[0*NCLS + lane+32]) + __ldg(&g_tsum[1*NCLS + lane+32])
                  + __ldg(&g_tsum[2*NCLS + lane+32]) + __ldg(&g_tsum[3*NCLS + lane+32]);
            pr2 = (t > 0) ? 1.f : 0.f;
        }
        float npres = pr + pr2;
        #pragma unroll
        for (int o = 16; o > 0; o >>= 1) npres += __shfl_xor_sync(0xffffffff, npres, o);
        if (lane == 0) {
            float ce_tot   = *(volatile float*)&g_ce2;
            float dice_tot = *(volatile float*)&g_dice2;
            float loss_ce = ce_tot / (float)(BN*QN);
            float ce_mask = g_ce_sum / fmaxf((float)g_nvalid, 1.f);
            float dice_loss = (npres - dice_tot / (float)(BN*QN)) / (float)NCLS;
            out[0] = 2.f*loss_ce + 5.f*ce_mask + 5.f*dice_loss;
        }
    }
}

extern "C" void kernel_launch(void* const* d_in, const int* in_sizes, int n_in,
                              void* d_out, int out_size)
{
    const float* logits  = (const float*)d_in[0];   // [4,100,41] f32
    const float* masks   = (const float*)d_in[1];   // [4,100,256,256] f32
    const int*   targets = (const int*)d_in[2];     // [4,256,256] i32
    float* out = (float*)d_out;

    zero_k<<<(BN*QN*NCLS + 255)/256, 256>>>();
    main_k<<<NBLK_MAIN, THREADS>>>(masks, targets);
    combine_k<<<NPIX/4/THREADS, THREADS>>>(targets);
    fin_k<<<FIN_BLOCKS, 128>>>(logits, out);
}

// round 11
// speedup vs baseline: 1.7729x; 1.0248x over previous
#include <cuda_runtime.h>
#include <math.h>

#define NCLS 40
#define QN 100
#define BN 4
#define HW 65536
#define THREADS 256
#define PPT 4
#define PIX (THREADS*PPT)          // 1024 pixels per block
#define NC1 (NCLS+1)
#define QG 4                       // q-groups
#define QPG (QN/QG)                // 25 queries per group
#define NPIX (BN*HW)               // 262144 pixels
#define PIXBLK (HW/PIX)            // 64 pixel-blocks per image
#define NBLK_MAIN (QG*BN*PIXBLK)   // 1024
#define FIN_WARPS (BN*QN)          // 400
#define FIN_BLOCKS 100             // 4 warps per block

// ---- scratch (device globals; no allocation allowed) ----
__device__ float g_inter[BN*QN*NCLS];
__device__ float g_src[BN*QN];
__device__ int   g_counts[BN*QN*NCLS];
__device__ int   g_tsum[BN*NCLS];
__device__ float g_ce_sum;
__device__ int   g_nvalid;
__device__ float g_ce2, g_dice2;
__device__ int   g_done;
// per-pixel per-group partials (~13.6 MB)
__device__ float4 g_pssum[QG][NPIX/4];
__device__ float4 g_pmax [QG][NPIX/4];
__device__ float4 g_pxt  [QG][NPIX/4];
__device__ uchar4 g_pamax[QG][NPIX/4];

__global__ void zero_k() {
    int i = blockIdx.x * blockDim.x + threadIdx.x;
    if (i < BN*QN*NCLS) { g_inter[i] = 0.f; g_counts[i] = 0; }
    if (i < BN*QN) g_src[i] = 0.f;
    if (i < BN*NCLS) g_tsum[i] = 0;
    if (i == 0) { g_ce_sum = 0.f; g_nvalid = 0; g_ce2 = 0.f; g_dice2 = 0.f; g_done = 0; }
}

// Streaming pass: block = (q-group, image, 1024 pixels).
// One q per barrier, float4/thread, depth-2 register prefetch ring.
// inter[q][c] via class-sorted shared staging; 2-ATOMS commit structure.
__global__ __launch_bounds__(THREADS) void main_k(
    const float* __restrict__ masks, const int* __restrict__ targets)
{
    __shared__ __align__(16) float sig_sh[2][PIX];  // double buffer: 1 barrier per q
    __shared__ float inter_sh[QPG*NC1];             // 4.1 KB, class 40 = ignore bin
    __shared__ unsigned char cls_sorted[PIX];
    __shared__ int s_cnt[NC1];
    __shared__ int s_base[NC1];
    __shared__ int s_cur[NC1];

    const int tid = threadIdx.x;
    const int g   = blockIdx.x / (BN*PIXBLK);
    const int rem = blockIdx.x % (BN*PIXBLK);
    const int img = rem / PIXBLK;
    const int blk = rem % PIXBLK;
    const int q0  = g*QPG;
    const int pixbase = img*HW + blk*PIX;

    for (int i = tid; i < QPG*NC1; i += THREADS) inter_sh[i] = 0.f;
    for (int i = tid; i < NC1; i += THREADS) s_cnt[i] = 0;
    __syncthreads();

    // ---- classes (4 contiguous pixels/thread) + counting sort by class ----
    int myc[PPT], mypos[PPT];
    {
        int4 t4 = reinterpret_cast<const int4*>(targets + pixbase)[tid];
        int tt[PPT] = {t4.x, t4.y, t4.z, t4.w};
        #pragma unroll
        for (int j = 0; j < PPT; j++) {
            myc[j] = ((unsigned)tt[j] < (unsigned)NCLS) ? tt[j] : NCLS; // 40 == ignore
            atomicAdd(&s_cnt[myc[j]], 1);
        }
    }
    __syncthreads();
    if (tid == 0) {
        int r = 0;
        for (int c = 0; c < NC1; c++) { s_base[c] = r; r += s_cnt[c]; }
    }
    __syncthreads();
    for (int i = tid; i < NC1; i += THREADS) s_cur[i] = s_base[i];
    __syncthreads();
    #pragma unroll
    for (int j = 0; j < PPT; j++) {
        mypos[j] = atomicAdd(&s_cur[myc[j]], 1);
        cls_sorted[mypos[j]] = (unsigned char)myc[j];
    }
    __syncthreads();
    int k0, k1, k2, k3;     // classes of my 4 sorted gather slots (non-decreasing)
    k0 = (int)cls_sorted[tid*PPT + 0];
    k1 = (int)cls_sorted[tid*PPT + 1];
    k2 = (int)cls_sorted[tid*PPT + 2];
    k3 = (int)cls_sorted[tid*PPT + 3];

    float ssum[PPT], mmax[PPT], xt[PPT];
    int amax[PPT];
    #pragma unroll
    for (int j = 0; j < PPT; j++) { ssum[j] = 0.f; mmax[j] = -1e30f; xt[j] = 0.f; amax[j] = q0; }

    const float4* base4 = reinterpret_cast<const float4*>(
        masks + (size_t)img*QN*HW + (size_t)blk*PIX);
    const int stride4 = HW/4;

    // depth-2 prefetch ring
    float4 cur = base4[(size_t)q0*stride4 + tid];
    float4 nx1 = base4[(size_t)(q0+1)*stride4 + tid];
    for (int qi = 0; qi < QPG; qi++) {
        const int q = q0 + qi;
        float4 nx2;
        if (qi + 2 < QPG) nx2 = base4[(size_t)(q+2)*stride4 + tid];
        else nx2 = make_float4(0.f, 0.f, 0.f, 0.f);

        float xv[PPT] = {cur.x, cur.y, cur.z, cur.w};
        float* sbuf = sig_sh[qi & 1];
        #pragma unroll
        for (int j = 0; j < PPT; j++) {
            float x = xv[j];
            if (x > mmax[j]) { mmax[j] = x; amax[j] = q; }
            xt[j] = (q == myc[j]) ? x : xt[j];
            float t = __expf(x);               // one exp serves both lse and sigmoid
            ssum[j] += t;
            float sg = __fdividef(t, 1.f + t); // sigmoid
            sbuf[mypos[j]] = sg;               // scatter to class-sorted slot
        }
        __syncthreads();
        // gather 4 consecutive class-sorted slots; commit with ~2 ATOMS:
        // sorted k0<=k1<=k2<=k3 -> sum-into-k0 always; k3 if different; middles rare
        float4 v = reinterpret_cast<const float4*>(sbuf)[tid];
        float* ip = &inter_sh[qi*NC1];
        float s0 = v.x;
        if (k1 == k0) s0 += v.y;
        if (k2 == k0) s0 += v.z;
        if (k3 == k0) s0 += v.w;
        atomicAdd(ip + k0, s0);
        if (__any_sync(0xffffffffu, k3 != k0)) {
            if (k3 != k0) {
                float s3 = v.w;
                if (k2 == k3) s3 += v.z;
                if (k1 == k3) s3 += v.y;
                atomicAdd(ip + k3, s3);
            }
            bool m1 = (k1 != k0) & (k1 != k3);
            bool m2 = (k2 != k0) & (k2 != k3);
            if (__any_sync(0xffffffffu, m1 | m2)) {
                if (m1) atomicAdd(ip + k1, v.y);
                if (m2) atomicAdd(ip + k2, v.z);
            }
        }
        cur = nx1; nx1 = nx2;
        // no 2nd barrier: next q writes the other buffer; its barrier orders reuse
    }

    // ---- write per-pixel partials for combine_k ----
    {
        const int p4 = pixbase/4 + tid;
        g_pssum[g][p4] = make_float4(ssum[0], ssum[1], ssum[2], ssum[3]);
        g_pmax [g][p4] = make_float4(mmax[0], mmax[1], mmax[2], mmax[3]);
        g_pxt  [g][p4] = make_float4(xt[0], xt[1], xt[2], xt[3]);
        g_pamax[g][p4] = make_uchar4((unsigned char)amax[0], (unsigned char)amax[1],
                                     (unsigned char)amax[2], (unsigned char)amax[3]);
    }
    __syncthreads();   // orders all inter_sh atomics before flush

    // ---- flush inter_sh -> global (src_sum = sum over all 41 bins incl. ignore) ----
    for (int qi = tid; qi < QPG; qi += THREADS) {
        float ss = 0.f;
        const int q = q0 + qi;
        #pragma unroll 1
        for (int c = 0; c < NC1; c++) {
            float v = inter_sh[qi*NC1 + c];
            ss += v;
            if (c < NCLS) atomicAdd(&g_inter[(img*QN + q)*NCLS + c], v);
        }
        atomicAdd(&g_src[img*QN + q], ss);
    }
}

// Cross-group combine: per-pixel ce_mask numerator, n_valid, assignment counts,
// and the per-image class histogram (== tsum, since Sum_q counts is q-free).
__global__ __launch_bounds__(THREADS) void combine_k(const int* __restrict__ targets)
{
    __shared__ float s_ce[8];
    __shared__ float s_nv[8];
    __shared__ int hist[NCLS];
    const int tid = threadIdx.x;
    const int lane = tid & 31;
    const int wid = tid >> 5;
    const int j = blockIdx.x * THREADS + tid;      // float4 pixel group
    const int img = (int)(((size_t)blockIdx.x * THREADS * 4) >> 16);

    for (int i = tid; i < NCLS; i += THREADS) hist[i] = 0;
    __syncthreads();

    float4 ssum = g_pssum[0][j];
    float4 mmax = g_pmax [0][j];
    float4 xt   = g_pxt  [0][j];
    uchar4 am   = g_pamax[0][j];
    #pragma unroll
    for (int g = 1; g < QG; g++) {
        float4 s2 = g_pssum[g][j];
        float4 m2 = g_pmax [g][j];
        float4 x2 = g_pxt  [g][j];
        uchar4 a2 = g_pamax[g][j];
        ssum.x += s2.x; ssum.y += s2.y; ssum.z += s2.z; ssum.w += s2.w;
        xt.x += x2.x; xt.y += x2.y; xt.z += x2.z; xt.w += x2.w;
        if (m2.x > mmax.x) { mmax.x = m2.x; am.x = a2.x; }
        if (m2.y > mmax.y) { mmax.y = m2.y; am.y = a2.y; }
        if (m2.z > mmax.z) { mmax.z = m2.z; am.z = a2.z; }
        if (m2.w > mmax.w) { mmax.w = m2.w; am.w = a2.w; }
    }
    int4 t4 = reinterpret_cast<const int4*>(targets)[j];

    float ce_l = 0.f, nv = 0.f;
    int tt[PPT] = {t4.x, t4.y, t4.z, t4.w};
    float ssv[PPT] = {ssum.x, ssum.y, ssum.z, ssum.w};
    float xtv[PPT] = {xt.x, xt.y, xt.z, xt.w};
    int amv[PPT] = {am.x, am.y, am.z, am.w};
    #pragma unroll
    for (int k = 0; k < PPT; k++) {
        if ((unsigned)tt[k] < (unsigned)NCLS) {
            ce_l += __logf(ssv[k]) - xtv[k];       // lse - x[target]
            nv += 1.f;
            atomicAdd(&hist[tt[k]], 1);
            atomicAdd(&g_counts[(img*QN + amv[k])*NCLS + tt[k]], 1);
        }
    }
    // warp-shuffle reduce, then cross-warp via shared
    #pragma unroll
    for (int o = 16; o > 0; o >>= 1) {
        ce_l += __shfl_xor_sync(0xffffffffu, ce_l, o);
        nv   += __shfl_xor_sync(0xffffffffu, nv, o);
    }
    if (lane == 0) { s_ce[wid] = ce_l; s_nv[wid] = nv; }
    __syncthreads();
    if (wid == 0) {
        float c = (lane < 8) ? s_ce[lane] : 0.f;
        float n = (lane < 8) ? s_nv[lane] : 0.f;
        #pragma unroll
        for (int o = 4; o > 0; o >>= 1) {
            c += __shfl_xor_sync(0xffffffffu, c, o);
            n += __shfl_xor_sync(0xffffffffu, n, o);
        }
        if (lane == 0) { atomicAdd(&g_ce_sum, c); atomicAdd(&g_nvalid, (int)n); }
    }
    // flush class histogram
    for (int c = tid; c < NCLS; c += THREADS)
        if (hist[c]) atomicAdd(&g_tsum[img*NCLS + c], hist[c]);
}

// Warp-per-(b,q) final reduction: lane-parallel mode/CE/dice; last warp finalizes.
__global__ __launch_bounds__(128) void fin_k(const float* __restrict__ logits,
                                             float* __restrict__ out)
{
    const int tid  = threadIdx.x;
    const int lane = tid & 31;
    const int item = blockIdx.x * 4 + (tid >> 5);   // (b,q), < 400
    const int b = item / QN;

    // ---- mode label: packed-key warp max; key = (count<<16)|(NCLS-c) ----
    const int* cp = &g_counts[item*NCLS];
    int c1 = lane, c2 = lane + 32;
    int v1 = __ldg(cp + c1);
    int v2 = (c2 < NCLS) ? __ldg(cp + c2) : 0;
    long long kk1 = ((long long)v1 << 16) | (NCLS - c1);
    long long kk2 = (c2 < NCLS) ? (((long long)v2 << 16) | (NCLS - c2)) : 0;
    long long key = kk1 > kk2 ? kk1 : kk2;
    #pragma unroll
    for (int o = 16; o > 0; o >>= 1) {
        long long other = __shfl_xor_sync(0xffffffff, key, o);
        if (other > key) key = other;
    }
    int bestcnt = (int)(key >> 16);
    int bestc = NCLS - (int)(key & 0xffff);

    // ---- focal CE over 41 logits (warp softmax) ----
    float ce_term = 0.f;
    if (bestcnt > 0) {
        const float* lg = logits + item*NC1;
        float a = __ldg(lg + lane);
        float bb = (lane < NC1 - 32) ? __ldg(lg + lane + 32) : -1e30f;
        float m = fmaxf(a, bb);
        #pragma unroll
        for (int o = 16; o > 0; o >>= 1) m = fmaxf(m, __shfl_xor_sync(0xffffffff, m, o));
        float s = __expf(a - m) + ((lane < NC1 - 32) ? __expf(bb - m) : 0.f);
        #pragma unroll
        for (int o = 16; o > 0; o >>= 1) s += __shfl_xor_sync(0xffffffff, s, o);
        float lgb = __shfl_sync(0xffffffff, (bestc < 32) ? a : bb, bestc & 31);
        float nll = m + __logf(s) - lgb;
        float p = __expf(-nll);
        float om = 1.f - p;
        ce_term = om * om * nll;
    }

    // ---- dice terms: lanes cover classes lane, lane+32 ----
    float ss = __ldg(&g_src[item]);
    float dice_l = 0.f;
    {
        float t0 = (float)__ldg(&g_tsum[0*NCLS + c1]);
        float t1 = (float)__ldg(&g_tsum[1*NCLS + c1]);
        float t2 = (float)__ldg(&g_tsum[2*NCLS + c1]);
        float t3 = (float)__ldg(&g_tsum[3*NCLS + c1]);
        float pres = (t0 + t1 + t2 + t3 > 0.f) ? 1.f : 0.f;
        float tb = (b == 0) ? t0 : (b == 1) ? t1 : (b == 2) ? t2 : t3;
        dice_l += pres * 2.f * __ldg(&g_inter[item*NCLS + c1]) / (ss + tb + 1e-8f);
        if (c2 < NCLS) {
            float u0 = (float)__ldg(&g_tsum[0*NCLS + c2]);
            float u1 = (float)__ldg(&g_tsum[1*NCLS + c2]);
            float u2 = (float)__ldg(&g_tsum[2*NCLS + c2]);
            float u3 = (float)__ldg(&g_tsum[3*NCLS + c2]);
            float pres2 = (u0 + u1 + u2 + u3 > 0.f) ? 1.f : 0.f;
            float ub = (b == 0) ? u0 : (b == 1) ? u1 : (b == 2) ? u2 : u3;
            dice_l += pres2 * 2.f * __ldg(&g_inter[item*NCLS + c2]) / (ss + ub + 1e-8f);
        }
    }
    #pragma unroll
    for (int o = 16; o > 0; o >>= 1) dice_l += __shfl_xor_sync(0xffffffff, dice_l, o);

    bool last = false;
    if (lane == 0) {
        atomicAdd(&g_ce2, ce_term);
        atomicAdd(&g_dice2, dice_l);
        __threadfence();
        last = (atomicAdd(&g_done, 1) == FIN_WARPS - 1);
    }
    if (__shfl_sync(0xffffffff, last ? 1 : 0, 0)) {
        float pr = 0.f;
        if (lane < NCLS) {
            int t = __ldg(&g_tsum[0*NCLS + lane]) + __ldg(&g_tsum[1*NCLS + lane])
                  + __ldg(&g_tsum[2*NCLS + lane]) + __ldg(&g_tsum[3*NCLS + lane]);
            pr = (t > 0) ? 1.f : 0.f;
        }
        float pr2 = 0.f;
        if (lane + 32 < NCLS) {
            int t = __ldg(&g_tsum[0*NCLS + lane+32]) + __ldg(&g_tsum[1*NCLS + lane+32])
                  + __ldg(&g_tsum[2*NCLS + lane+32]) + __ldg(&g_tsum[3*NCLS + lane+32]);
            pr2 = (t > 0) ? 1.f : 0.f;
        }
        float npres = pr + pr2;
        #pragma unroll
        for (int o = 16; o > 0; o >>= 1) npres += __shfl_xor_sync(0xffffffff, npres, o);
        if (lane == 0) {
            float ce_tot   = *(volatile float*)&g_ce2;
            float dice_tot = *(volatile float*)&g_dice2;
            float loss_ce = ce_tot / (float)(BN*QN);
            float ce_mask = g_ce_sum / fmaxf((float)g_nvalid, 1.f);
            float dice_loss = (npres - dice_tot / (float)(BN*QN)) / (float)NCLS;
            out[0] = 2.f*loss_ce + 5.f*ce_mask + 5.f*dice_loss;
        }
    }
}

extern "C" void kernel_launch(void* const* d_in, const int* in_sizes, int n_in,
                              void* d_out, int out_size)
{
    const float* logits  = (const float*)d_in[0];   // [4,100,41] f32
    const float* masks   = (const float*)d_in[1];   // [4,100,256,256] f32
    const int*   targets = (const int*)d_in[2];     // [4,256,256] i32
    float* out = (float*)d_out;

    zero_k<<<(BN*QN*NCLS + 255)/256, 256>>>();
    main_k<<<NBLK_MAIN, THREADS>>>(masks, targets);
    combine_k<<<NPIX/4/THREADS, THREADS>>>(targets);
    fin_k<<<FIN_BLOCKS, 128>>>(logits, out);
}

// round 12
// speedup vs baseline: 1.8595x; 1.0489x over previous
#include <cuda_runtime.h>
#include <math.h>

#define NCLS 40
#define QN 100
#define BN 4
#define HW 65536
#define THREADS 256
#define NWARP (THREADS/32)
#define PPT 4
#define PIX (THREADS*PPT)          // 1024 pixels per block
#define WPIX 128                   // pixels per warp
#define NC1 (NCLS+1)
#define QG 4                       // q-groups
#define QPG (QN/QG)                // 25 queries per group
#define NPIX (BN*HW)               // 262144 pixels
#define PIXBLK (HW/PIX)            // 64 pixel-blocks per image
#define NBLK_MAIN (QG*BN*PIXBLK)   // 1024
#define FIN_WARPS (BN*QN)          // 400
#define FIN_BLOCKS 100             // 4 warps per block

// ---- scratch (device globals; no allocation allowed) ----
__device__ float g_inter[BN*QN*NCLS];
__device__ float g_src[BN*QN];
__device__ int   g_counts[BN*QN*NCLS];
__device__ int   g_tsum[BN*NCLS];
__device__ float g_ce_sum;
__device__ int   g_nvalid;
__device__ float g_ce2, g_dice2;
__device__ int   g_done;
// per-pixel per-group partials (~13.6 MB)
__device__ float4 g_pssum[QG][NPIX/4];
__device__ float4 g_pmax [QG][NPIX/4];
__device__ float4 g_pxt  [QG][NPIX/4];
__device__ uchar4 g_pamax[QG][NPIX/4];

__global__ void zero_k() {
    int i = blockIdx.x * blockDim.x + threadIdx.x;
    if (i < BN*QN*NCLS) { g_inter[i] = 0.f; g_counts[i] = 0; }
    if (i < BN*QN) g_src[i] = 0.f;
    if (i < BN*NCLS) g_tsum[i] = 0;
    if (i == 0) { g_ce_sum = 0.f; g_nvalid = 0; g_ce2 = 0.f; g_dice2 = 0.f; g_done = 0; }
}

// Streaming pass: block = (q-group, image, 1024 pixels), 8 independent warps.
// WARP-LOCAL counting sort + staging: no __syncthreads in the q-loop — each
// warp scatters/gathers in its own 128-slot buffer with one __syncwarp per q.
// inter[q][c] accumulated via shared atomics (barrier-free).
__global__ __launch_bounds__(THREADS) void main_k(
    const float* __restrict__ masks, const int* __restrict__ targets)
{
    __shared__ __align__(16) float sig_sh[2][NWARP][WPIX];  // 8 KB double buffer
    __shared__ float inter_sh[QPG*NC1];                     // 4.1 KB
    __shared__ unsigned char cls_sorted[NWARP][WPIX];       // 1 KB
    __shared__ int wcnt[NWARP][NC1];
    __shared__ int wbase[NWARP][NC1];
    __shared__ int wcur[NWARP][NC1];

    const int tid  = threadIdx.x;
    const int lane = tid & 31;
    const int w    = tid >> 5;
    const int g    = blockIdx.x / (BN*PIXBLK);
    const int rem  = blockIdx.x % (BN*PIXBLK);
    const int img  = rem / PIXBLK;
    const int blk  = rem % PIXBLK;
    const int q0   = g*QPG;
    const int pixbase = img*HW + blk*PIX;

    for (int i = tid; i < QPG*NC1; i += THREADS) inter_sh[i] = 0.f;
    for (int i = lane; i < NC1; i += 32) wcnt[w][i] = 0;
    __syncthreads();   // the only block barrier before the loop

    // ---- classes (4 contiguous pixels/lane) + WARP-LOCAL counting sort ----
    int myc[PPT], mypos[PPT];
    {
        int4 t4 = reinterpret_cast<const int4*>(targets + pixbase)[w*32 + lane];
        int tt[PPT] = {t4.x, t4.y, t4.z, t4.w};
        #pragma unroll
        for (int j = 0; j < PPT; j++) {
            myc[j] = ((unsigned)tt[j] < (unsigned)NCLS) ? tt[j] : NCLS; // 40 == ignore
            atomicAdd(&wcnt[w][myc[j]], 1);
        }
    }
    __syncwarp();
    if (lane == 0) {
        int r = 0;
        for (int c = 0; c < NC1; c++) { wbase[w][c] = r; r += wcnt[w][c]; }
    }
    __syncwarp();
    for (int i = lane; i < NC1; i += 32) wcur[w][i] = wbase[w][i];
    __syncwarp();
    #pragma unroll
    for (int j = 0; j < PPT; j++) {
        mypos[j] = atomicAdd(&wcur[w][myc[j]], 1);
        cls_sorted[w][mypos[j]] = (unsigned char)myc[j];
    }
    __syncwarp();
    const int k0 = (int)cls_sorted[w][lane*PPT + 0];
    const int k1 = (int)cls_sorted[w][lane*PPT + 1];
    const int k2 = (int)cls_sorted[w][lane*PPT + 2];
    const int k3 = (int)cls_sorted[w][lane*PPT + 3];

    float ssum[PPT], mmax[PPT], xt[PPT];
    int amax[PPT];
    #pragma unroll
    for (int j = 0; j < PPT; j++) { ssum[j] = 0.f; mmax[j] = -1e30f; xt[j] = 0.f; amax[j] = q0; }

    const float4* base4 = reinterpret_cast<const float4*>(
        masks + (size_t)img*QN*HW + (size_t)blk*PIX);
    const int stride4 = HW/4;
    const int myf4 = w*32 + lane;     // this thread's float4 slot (== old tid)

    float4 cur = base4[(size_t)q0*stride4 + myf4];    // prefetch first q
    for (int qi = 0; qi < QPG; qi++) {
        const int q = q0 + qi;
        float4 nxt;
        if (qi + 1 < QPG) nxt = base4[(size_t)(q+1)*stride4 + myf4];
        else nxt = make_float4(0.f, 0.f, 0.f, 0.f);

        float xv[PPT] = {cur.x, cur.y, cur.z, cur.w};
        float* sbuf = sig_sh[qi & 1][w];
        #pragma unroll
        for (int j = 0; j < PPT; j++) {
            float x = xv[j];
            if (x > mmax[j]) { mmax[j] = x; amax[j] = q; }
            xt[j] = (q == myc[j]) ? x : xt[j];
            float t = __expf(x);               // one exp serves both lse and sigmoid
            ssum[j] += t;
            sbuf[mypos[j]] = __fdividef(t, 1.f + t);  // sigmoid -> sorted slot
        }
        __syncwarp();                          // warp-local scatter->gather
        // gather 4 consecutive class-sorted slots; run-merge; commit
        float4 v = reinterpret_cast<const float4*>(sbuf)[lane];
        float* ip = &inter_sh[qi*NC1];
        float s0 = v.x;
        if (k1 == k0) s0 += v.y;
        if (k2 == k0) s0 += v.z;
        if (k3 == k0) s0 += v.w;
        atomicAdd(ip + k0, s0);
        if (__any_sync(0xffffffffu, k3 != k0)) {
            if (k3 != k0) {
                float s3 = v.w;
                if (k2 == k3) s3 += v.z;
                if (k1 == k3) s3 += v.y;
                atomicAdd(ip + k3, s3);
            }
            bool m1 = (k1 != k0) & (k1 != k3);
            bool m2 = (k2 != k0) & (k2 != k3);
            if (__any_sync(0xffffffffu, m1 | m2)) {
                if (m1) atomicAdd(ip + k1, v.y);
                if (m2) atomicAdd(ip + k2, v.z);
            }
        }
        cur = nxt;
        // no barrier: double buffer; this warp's next scatter uses other buffer
    }

    // ---- write per-pixel partials for combine_k ----
    {
        const int p4 = pixbase/4 + myf4;
        g_pssum[g][p4] = make_float4(ssum[0], ssum[1], ssum[2], ssum[3]);
        g_pmax [g][p4] = make_float4(mmax[0], mmax[1], mmax[2], mmax[3]);
        g_pxt  [g][p4] = make_float4(xt[0], xt[1], xt[2], xt[3]);
        g_pamax[g][p4] = make_uchar4((unsigned char)amax[0], (unsigned char)amax[1],
                                     (unsigned char)amax[2], (unsigned char)amax[3]);
    }
    __syncthreads();   // orders all inter_sh atomics before flush

    // ---- flush inter_sh -> global (src_sum = sum over all 41 bins incl. ignore) ----
    for (int qi = tid; qi < QPG; qi += THREADS) {
        float ss = 0.f;
        const int q = q0 + qi;
        #pragma unroll 1
        for (int c = 0; c < NC1; c++) {
            float v = inter_sh[qi*NC1 + c];
            ss += v;
            if (c < NCLS) atomicAdd(&g_inter[(img*QN + q)*NCLS + c], v);
        }
        atomicAdd(&g_src[img*QN + q], ss);
    }
}

// Cross-group combine: per-pixel ce_mask numerator, n_valid, assignment counts,
// and the per-image class histogram (== tsum, since Sum_q counts is q-free).
__global__ __launch_bounds__(THREADS) void combine_k(const int* __restrict__ targets)
{
    __shared__ float s_ce[8];
    __shared__ float s_nv[8];
    __shared__ int hist[NCLS];
    const int tid = threadIdx.x;
    const int lane = tid & 31;
    const int wid = tid >> 5;
    const int j = blockIdx.x * THREADS + tid;      // float4 pixel group
    const int img = (int)(((size_t)blockIdx.x * THREADS * 4) >> 16);

    for (int i = tid; i < NCLS; i += THREADS) hist[i] = 0;
    __syncthreads();

    float4 ssum = g_pssum[0][j];
    float4 mmax = g_pmax [0][j];
    float4 xt   = g_pxt  [0][j];
    uchar4 am   = g_pamax[0][j];
    #pragma unroll
    for (int g = 1; g < QG; g++) {
        float4 s2 = g_pssum[g][j];
        float4 m2 = g_pmax [g][j];
        float4 x2 = g_pxt  [g][j];
        uchar4 a2 = g_pamax[g][j];
        ssum.x += s2.x; ssum.y += s2.y; ssum.z += s2.z; ssum.w += s2.w;
        xt.x += x2.x; xt.y += x2.y; xt.z += x2.z; xt.w += x2.w;
        if (m2.x > mmax.x) { mmax.x = m2.x; am.x = a2.x; }
        if (m2.y > mmax.y) { mmax.y = m2.y; am.y = a2.y; }
        if (m2.z > mmax.z) { mmax.z = m2.z; am.z = a2.z; }
        if (m2.w > mmax.w) { mmax.w = m2.w; am.w = a2.w; }
    }
    int4 t4 = reinterpret_cast<const int4*>(targets)[j];

    float ce_l = 0.f, nv = 0.f;
    int tt[PPT] = {t4.x, t4.y, t4.z, t4.w};
    float ssv[PPT] = {ssum.x, ssum.y, ssum.z, ssum.w};
    float xtv[PPT] = {xt.x, xt.y, xt.z, xt.w};
    int amv[PPT] = {am.x, am.y, am.z, am.w};
    #pragma unroll
    for (int k = 0; k < PPT; k++) {
        if ((unsigned)tt[k] < (unsigned)NCLS) {
            ce_l += __logf(ssv[k]) - xtv[k];       // lse - x[target]
            nv += 1.f;
            atomicAdd(&hist[tt[k]], 1);
            atomicAdd(&g_counts[(img*QN + amv[k])*NCLS + tt[k]], 1);
        }
    }
    // warp-shuffle reduce, then cross-warp via shared
    #pragma unroll
    for (int o = 16; o > 0; o >>= 1) {
        ce_l += __shfl_xor_sync(0xffffffffu, ce_l, o);
        nv   += __shfl_xor_sync(0xffffffffu, nv, o);
    }
    if (lane == 0) { s_ce[wid] = ce_l; s_nv[wid] = nv; }
    __syncthreads();
    if (wid == 0) {
        float c = (lane < 8) ? s_ce[lane] : 0.f;
        float n = (lane < 8) ? s_nv[lane] : 0.f;
        #pragma unroll
        for (int o = 4; o > 0; o >>= 1) {
            c += __shfl_xor_sync(0xffffffffu, c, o);
            n += __shfl_xor_sync(0xffffffffu, n, o);
        }
        if (lane == 0) { atomicAdd(&g_ce_sum, c); atomicAdd(&g_nvalid, (int)n); }
    }
    // flush class histogram
    for (int c = tid; c < NCLS; c += THREADS)
        if (hist[c]) atomicAdd(&g_tsum[img*NCLS + c], hist[c]);
}

// Warp-per-(b,q) final reduction: lane-parallel mode/CE/dice; last warp finalizes.
__global__ __launch_bounds__(128) void fin_k(const float* __restrict__ logits,
                                             float* __restrict__ out)
{
    const int tid  = threadIdx.x;
    const int lane = tid & 31;
    const int item = blockIdx.x * 4 + (tid >> 5);   // (b,q), < 400
    const int b = item / QN;

    // ---- mode label: packed-key warp max; key = (count<<16)|(NCLS-c) ----
    const int* cp = &g_counts[item*NCLS];
    int c1 = lane, c2 = lane + 32;
    int v1 = __ldg(cp + c1);
    int v2 = (c2 < NCLS) ? __ldg(cp + c2) : 0;
    long long kk1 = ((long long)v1 << 16) | (NCLS - c1);
    long long kk2 = (c2 < NCLS) ? (((long long)v2 << 16) | (NCLS - c2)) : 0;
    long long key = kk1 > kk2 ? kk1 : kk2;
    #pragma unroll
    for (int o = 16; o > 0; o >>= 1) {
        long long other = __shfl_xor_sync(0xffffffff, key, o);
        if (other > key) key = other;
    }
    int bestcnt = (int)(key >> 16);
    int bestc = NCLS - (int)(key & 0xffff);

    // ---- focal CE over 41 logits (warp softmax) ----
    float ce_term = 0.f;
    if (bestcnt > 0) {
        const float* lg = logits + item*NC1;
        float a = __ldg(lg + lane);
        float bb = (lane < NC1 - 32) ? __ldg(lg + lane + 32) : -1e30f;
        float m = fmaxf(a, bb);
        #pragma unroll
        for (int o = 16; o > 0; o >>= 1) m = fmaxf(m, __shfl_xor_sync(0xffffffff, m, o));
        float s = __expf(a - m) + ((lane < NC1 - 32) ? __expf(bb - m) : 0.f);
        #pragma unroll
        for (int o = 16; o > 0; o >>= 1) s += __shfl_xor_sync(0xffffffff, s, o);
        float lgb = __shfl_sync(0xffffffff, (bestc < 32) ? a : bb, bestc & 31);
        float nll = m + __logf(s) - lgb;
        float p = __expf(-nll);
        float om = 1.f - p;
        ce_term = om * om * nll;
    }

    // ---- dice terms: lanes cover classes lane, lane+32 ----
    float ss = __ldg(&g_src[item]);
    float dice_l = 0.f;
    {
        float t0 = (float)__ldg(&g_tsum[0*NCLS + c1]);
        float t1 = (float)__ldg(&g_tsum[1*NCLS + c1]);
        float t2 = (float)__ldg(&g_tsum[2*NCLS + c1]);
        float t3 = (float)__ldg(&g_tsum[3*NCLS + c1]);
        float pres = (t0 + t1 + t2 + t3 > 0.f) ? 1.f : 0.f;
        float tb = (b == 0) ? t0 : (b == 1) ? t1 : (b == 2) ? t2 : t3;
        dice_l += pres * 2.f * __ldg(&g_inter[item*NCLS + c1]) / (ss + tb + 1e-8f);
        if (c2 < NCLS) {
            float u0 = (float)__ldg(&g_tsum[0*NCLS + c2]);
            float u1 = (float)__ldg(&g_tsum[1*NCLS + c2]);
            float u2 = (float)__ldg(&g_tsum[2*NCLS + c2]);
            float u3 = (float)__ldg(&g_tsum[3*NCLS + c2]);
            float pres2 = (u0 + u1 + u2 + u3 > 0.f) ? 1.f : 0.f;
            float ub = (b == 0) ? u0 : (b == 1) ? u1 : (b == 2) ? u2 : u3;
            dice_l += pres2 * 2.f * __ldg(&g_inter[item*NCLS + c2]) / (ss + ub + 1e-8f);
        }
    }
    #pragma unroll
    for (int o = 16; o > 0; o >>= 1) dice_l += __shfl_xor_sync(0xffffffff, dice_l, o);

    bool last = false;
    if (lane == 0) {
        atomicAdd(&g_ce2, ce_term);
        atomicAdd(&g_dice2, dice_l);
        __threadfence();
        last = (atomicAdd(&g_done, 1) == FIN_WARPS - 1);
    }
    if (__shfl_sync(0xffffffff, last ? 1 : 0, 0)) {
        float pr = 0.f;
        if (lane < NCLS) {
            int t = __ldg(&g_tsum[0*NCLS + lane]) + __ldg(&g_tsum[1*NCLS + lane])
                  + __ldg(&g_tsum[2*NCLS + lane]) + __ldg(&g_tsum[3*NCLS + lane]);
            pr = (t > 0) ? 1.f : 0.f;
        }
        float pr2 = 0.f;
        if (lane + 32 < NCLS) {
            int t = __ldg(&g_tsum[0*NCLS + lane+32]) + __ldg(&g_tsum[1*NCLS + lane+32])
                  + __ldg(&g_tsum[2*NCLS + lane+32]) + __ldg(&g_tsum[3*NCLS + lane+32]);
            pr2 = (t > 0) ? 1.f : 0.f;
        }
        float npres = pr + pr2;
        #pragma unroll
        for (int o = 16; o > 0; o >>= 1) npres += __shfl_xor_sync(0xffffffff, npres, o);
        if (lane == 0) {
            float ce_tot   = *(volatile float*)&g_ce2;
            float dice_tot = *(volatile float*)&g_dice2;
            float loss_ce = ce_tot / (float)(BN*QN);
            float ce_mask = g_ce_sum / fmaxf((float)g_nvalid, 1.f);
            float dice_loss = (npres - dice_tot / (float)(BN*QN)) / (float)NCLS;
            out[0] = 2.f*loss_ce + 5.f*ce_mask + 5.f*dice_loss;
        }
    }
}

extern "C" void kernel_launch(void* const* d_in, const int* in_sizes, int n_in,
                              void* d_out, int out_size)
{
    const float* logits  = (const float*)d_in[0];   // [4,100,41] f32
    const float* masks   = (const float*)d_in[1];   // [4,100,256,256] f32
    const int*   targets = (const int*)d_in[2];     // [4,256,256] i32
    float* out = (float*)d_out;

    zero_k<<<(BN*QN*NCLS + 255)/256, 256>>>();
    main_k<<<NBLK_MAIN, THREADS>>>(masks, targets);
    combine_k<<<NPIX/4/THREADS, THREADS>>>(targets);
    fin_k<<<FIN_BLOCKS, 128>>>(logits, out);
}